// round 12
// baseline (speedup 1.0000x reference)
#include <cuda_runtime.h>
#include <cuda_bf16.h>
#include <cstdint>

// CDGM: two rounds of fused "sigmoid attention" + small GEMMs.
//   gl = relu(x@Wgl+b); sq_i = |gl_i|^2
//   adj_ij = sigmoid(c2 - c1*sqrt(max(sq_i+sq_j-2 gl_i.gl_j,0)+eps))  (c2 if diff==0)
//   x' = (adj @ (x@Wgnn+b)) / rowsum(adj);  relu (layer0);  softmax (end)
// adj (8192^2) never materialized. Flash-style fused attention + tensor-core
// prep GEMMs, all bf16 mma.sync. KSPLIT=8 (512 CTAs, no solo-CTA stragglers),
// 3-stage cp.async ring with ONE barrier per iteration.

#define NROWS 8192
#define KSPLIT 8

// ---------------- scratch (device globals: no allocation allowed) ----------
__device__ __nv_bfloat16 g_xb[NROWS * 256];           // bf16 input (layer0: 256, layer1: 128)
__device__ __nv_bfloat16 g_wgl0[256 * 128];
__device__ __nv_bfloat16 g_wgnn0[256 * 128];
__device__ __nv_bfloat16 g_wgl1[128 * 64];
__device__ __nv_bfloat16 g_wgnn1[128 * 64];
__device__ __nv_bfloat16 g_glb[NROWS * 128];          // gl, bf16, row-major [N,F]
__device__ __nv_bfloat16 g_hb [NROWS * 128];          // h,  bf16, row-major [N,F]
__device__ float g_sq[NROWS];                         // |gl_i|^2 (from rounded bf16)
__device__ float g_Opart[KSPLIT * NROWS * 128];       // per-ksplit partial O (32 MB)
__device__ float g_degpart[KSPLIT * NROWS];           // per-ksplit partial deg

// ---------------- helpers --------------------------------------------------
__device__ __forceinline__ void mma16816(float* d, const uint32_t* a,
                                         uint32_t b0, uint32_t b1) {
    asm("mma.sync.aligned.m16n8k16.row.col.f32.bf16.bf16.f32 "
        "{%0,%1,%2,%3}, {%4,%5,%6,%7}, {%8,%9}, {%0,%1,%2,%3};"
        : "+f"(d[0]), "+f"(d[1]), "+f"(d[2]), "+f"(d[3])
        : "r"(a[0]), "r"(a[1]), "r"(a[2]), "r"(a[3]), "r"(b0), "r"(b1));
}

__device__ __forceinline__ void ldsm4(uint32_t& r0, uint32_t& r1, uint32_t& r2,
                                      uint32_t& r3, uint32_t a) {
    asm volatile("ldmatrix.sync.aligned.m8n8.x4.shared.b16 {%0,%1,%2,%3}, [%4];"
                 : "=r"(r0), "=r"(r1), "=r"(r2), "=r"(r3) : "r"(a));
}
__device__ __forceinline__ void ldsm4t(uint32_t& r0, uint32_t& r1, uint32_t& r2,
                                       uint32_t& r3, uint32_t a) {
    asm volatile("ldmatrix.sync.aligned.m8n8.x4.trans.shared.b16 {%0,%1,%2,%3}, [%4];"
                 : "=r"(r0), "=r"(r1), "=r"(r2), "=r"(r3) : "r"(a));
}

__device__ __forceinline__ void cpa16(void* dst, const void* src) {
    uint32_t d = (uint32_t)__cvta_generic_to_shared(dst);
    asm volatile("cp.async.cg.shared.global [%0], [%1], 16;" :: "r"(d), "l"(src));
}
__device__ __forceinline__ void cpa_commit() {
    asm volatile("cp.async.commit_group;");
}
template <int N>
__device__ __forceinline__ void cpa_wait() {
    asm volatile("cp.async.wait_group %0;" :: "n"(N));
}

__device__ __forceinline__ uint32_t pack_bf16(float lo, float hi) {
    uint32_t r;
    asm("cvt.rn.bf16x2.f32 %0, %1, %2;" : "=r"(r) : "f"(hi), "f"(lo));
    return r;
}

// adj entry via tanh form: sigmoid(z) = 0.5*tanh(z/2) + 0.5,
// z = c2 - c1*sqrt(d+eps) (z = c2 if d==0).  h1 = c1/2, h2 = c2/2.
__device__ __forceinline__ float sigm(float sq2, float s, float h1, float h2) {
    float d = fmaxf(fmaf(-2.f, s, sq2), 0.f);
    float u;
    asm("sqrt.approx.f32 %0, %1;" : "=f"(u) : "f"(d + 1.1920929e-7f));
    float zz = (d == 0.f) ? h2 : fmaf(-h1, u, h2);   // z/2, mask semantics
    float t;
    asm("tanh.approx.f32 %0, %1;" : "=f"(t) : "f"(zz));
    return fmaf(0.5f, t, 0.5f);
}

// ---------------- fused fp32 -> bf16 convert (feat + all weights) ----------
// Segment layout (float4 indices):
//   [0, 524288)            feat   -> g_xb     (8192*256/4)
//   [524288, 532480)       Wgl0   -> g_wgl0   (8192)
//   [532480, 540672)       Wgnn0  -> g_wgnn0  (8192)
//   [540672, 542720)       Wgl1   -> g_wgl1   (2048)
//   [542720, 544768)       Wgnn1  -> g_wgnn1  (2048)
__global__ void __launch_bounds__(256) cvt_all_kernel(
    const float* __restrict__ feat,
    const float* __restrict__ wgl0, const float* __restrict__ wgnn0,
    const float* __restrict__ wgl1, const float* __restrict__ wgnn1) {
    int i = blockIdx.x * 256 + threadIdx.x;
    const float* src;
    __nv_bfloat16* dst;
    int off;
    if (i < 524288)      { src = feat;  dst = g_xb;    off = 0; }
    else if (i < 532480) { src = wgl0;  dst = g_wgl0;  off = 524288; }
    else if (i < 540672) { src = wgnn0; dst = g_wgnn0; off = 532480; }
    else if (i < 542720) { src = wgl1;  dst = g_wgl1;  off = 540672; }
    else if (i < 544768) { src = wgnn1; dst = g_wgnn1; off = 542720; }
    else return;
    int j = i - off;
    float4 v = ((const float4*)src)[j];
    __nv_bfloat162* d2 = (__nv_bfloat162*)dst + j * 2;
    d2[0] = __floats2bfloat162_rn(v.x, v.y);
    d2[1] = __floats2bfloat162_rn(v.z, v.w);
}

// ---------------- tensor-core prep -----------------------------------------
// C[128, F] = xb[128, K] @ W[K, F] (+bias). blockIdx.y: 0 => gl (relu + sq),
// 1 => h. Double-buffered cp.async over K chunks of 64.
template <int K, int F>
__global__ void __launch_bounds__(256) prep_mma_kernel(
    const __nv_bfloat16* __restrict__ wgl, const __nv_bfloat16* __restrict__ wgnn,
    const float* __restrict__ bgl, const float* __restrict__ bgnn) {
    constexpr int KB   = 64;
    constexpr int XSTR = KB + 8;             // 72
    constexpr int WSTR = F + 8;              // 136 / 72
    constexpr int XTB  = 128 * XSTR;
    constexpr int WTB  = KB * WSTR;
    constexpr int NT   = F / 8;
    constexpr int NK   = K / KB;

    extern __shared__ __align__(16) __nv_bfloat16 psm[];
    __nv_bfloat16* xs = psm;                 // [2][128][XSTR]
    __nv_bfloat16* ws = psm + 2 * XTB;       // [2][KB][WSTR]

    const bool isGl = (blockIdx.y == 0);
    const __nv_bfloat16* W = isGl ? wgl : wgnn;
    const float* bias = isGl ? bgl : bgnn;
    __nv_bfloat16* dst = isGl ? g_glb : g_hb;

    int tid = threadIdx.x, lane = tid & 31, w = tid >> 5;
    int g = lane >> 2, t = lane & 3;
    int rowbase = blockIdx.x * 128;
    const __nv_bfloat16* xb = g_xb;

    uint32_t aoff = (uint32_t)(((lane & 7) + (((lane >> 3) & 1) << 3)) * XSTR +
                               ((lane >> 4) & 1) * 8) * 2;
    uint32_t boff = (uint32_t)(((lane & 7) + (((lane >> 3) & 1) << 3)) * WSTR +
                               ((lane >> 4) & 1) * 8) * 2;
    uint32_t xs_sh = (uint32_t)__cvta_generic_to_shared(xs);
    uint32_t ws_sh = (uint32_t)__cvta_generic_to_shared(ws);

    float acc[NT][4];
#pragma unroll
    for (int n = 0; n < NT; ++n)
#pragma unroll
        for (int c = 0; c < 4; ++c) acc[n][c] = 0.f;

    auto prefetch = [&](int s, int kt) {
#pragma unroll
        for (int i = tid; i < 128 * (KB / 8); i += 256) {
            int r = i / (KB / 8), c = i % (KB / 8);
            cpa16(&xs[s * XTB + r * XSTR + c * 8],
                  xb + (size_t)(rowbase + r) * K + kt + c * 8);
        }
#pragma unroll
        for (int i = tid; i < KB * (F / 8); i += 256) {
            int r = i / (F / 8), c = i % (F / 8);
            cpa16(&ws[s * WTB + r * WSTR + c * 8], W + (size_t)(kt + r) * F + c * 8);
        }
    };

    prefetch(0, 0);
    cpa_commit();

    for (int it = 0; it < NK; ++it) {
        int cur = it & 1;
        if (it + 1 < NK) {
            prefetch(cur ^ 1, (it + 1) * KB);
            cpa_commit();
            cpa_wait<1>();
        } else {
            cpa_wait<0>();
        }
        __syncthreads();

        uint32_t xbase = xs_sh + (uint32_t)(cur * XTB * 2) +
                         (uint32_t)(w * 16 * XSTR * 2) + aoff;
        uint32_t wbase = ws_sh + (uint32_t)(cur * WTB * 2) + boff;

#pragma unroll
        for (int kc = 0; kc < 4; ++kc) {
            uint32_t a[4];
            ldsm4(a[0], a[1], a[2], a[3], xbase + (uint32_t)(kc * 16) * 2);
#pragma unroll
            for (int ntp = 0; ntp < NT / 2; ++ntp) {
                uint32_t b0, b1, b2, b3;
                ldsm4t(b0, b1, b2, b3,
                       wbase + (uint32_t)((kc * 16) * WSTR + ntp * 16) * 2);
                mma16816(acc[2 * ntp],     a, b0, b1);
                mma16816(acc[2 * ntp + 1], a, b2, b3);
            }
        }
        __syncthreads();
    }

    // Epilogue: bias (+relu for gl), bf16 store, fused sq (gl only).
    int r0 = rowbase + w * 16 + g;
    int r1 = r0 + 8;
    float s0 = 0.f, s1 = 0.f;
#pragma unroll
    for (int nt = 0; nt < NT; ++nt) {
        int col = nt * 8 + 2 * t;
        float b0 = bias[col], b1 = bias[col + 1];
        float v00 = acc[nt][0] + b0, v01 = acc[nt][1] + b1;
        float v10 = acc[nt][2] + b0, v11 = acc[nt][3] + b1;
        if (isGl) {
            v00 = fmaxf(v00, 0.f); v01 = fmaxf(v01, 0.f);
            v10 = fmaxf(v10, 0.f); v11 = fmaxf(v11, 0.f);
        }
        uint32_t u0 = pack_bf16(v00, v01);
        uint32_t u1 = pack_bf16(v10, v11);
        *(uint32_t*)(dst + (size_t)r0 * F + col) = u0;
        *(uint32_t*)(dst + (size_t)r1 * F + col) = u1;
        if (isGl) {
            float2 q0 = __bfloat1622float2(*(__nv_bfloat162*)&u0);
            float2 q1 = __bfloat1622float2(*(__nv_bfloat162*)&u1);
            s0 = fmaf(q0.x, q0.x, fmaf(q0.y, q0.y, s0));
            s1 = fmaf(q1.x, q1.x, fmaf(q1.y, q1.y, s1));
        }
    }
    if (isGl) {
        s0 += __shfl_xor_sync(0xffffffffu, s0, 1);
        s0 += __shfl_xor_sync(0xffffffffu, s0, 2);
        s1 += __shfl_xor_sync(0xffffffffu, s1, 1);
        s1 += __shfl_xor_sync(0xffffffffu, s1, 2);
        if (t == 0) { g_sq[r0] = s0; g_sq[r1] = s1; }
    }
}

// ---------------- fused sigmoid-attention ----------------------------------
// BR=128 (8 warps x 16 rows), BC=64, grid (N/128, KSPLIT=8). Deterministic.
// 3-stage cp.async ring, ONE barrier per iteration (skew <= 1 => prefetch
// target (it+1)%3 never collides with readers of it%3 / (it-1)%3).
template <int F, int MINB>
__global__ void __launch_bounds__(256, MINB) attn_kernel(const float* __restrict__ temp,
                                                         const float* __restrict__ theta) {
    constexpr int KSTR  = F + 8;
    constexpr int TILEB = 64 * KSTR;
    constexpr int KC  = F / 16;
    constexpr int NT2 = F / 8;
    constexpr int CH  = F / 8;

    extern __shared__ __align__(16) __nv_bfloat16 dsm[];
    __nv_bfloat16* Ks = dsm;                      // [3][64][KSTR]
    __nv_bfloat16* Vs = dsm + 3 * TILEB;          // [3][64][KSTR]
    float* sqs = (float*)(dsm + 6 * TILEB);       // [3][64]

    int tid = threadIdx.x, lane = tid & 31, w = tid >> 5;
    int g = lane >> 2, t = lane & 3;
    int qrow0 = blockIdx.x * 128 + w * 16 + g;
    int qrow1 = qrow0 + 8;
    float h1 = 0.5f * (1.f + __ldg(temp)), h2 = 0.5f * (5.f + __ldg(theta));

    uint32_t aq[KC][4];
#pragma unroll
    for (int kc = 0; kc < KC; ++kc) {
        const __nv_bfloat16* q0 = g_glb + (size_t)qrow0 * F + kc * 16 + 2 * t;
        const __nv_bfloat16* q1 = g_glb + (size_t)qrow1 * F + kc * 16 + 2 * t;
        aq[kc][0] = *(const uint32_t*)q0;
        aq[kc][1] = *(const uint32_t*)q1;
        aq[kc][2] = *(const uint32_t*)(q0 + 8);
        aq[kc][3] = *(const uint32_t*)(q1 + 8);
    }
    float sqi0 = g_sq[qrow0], sqi1 = g_sq[qrow1];

    float oacc[NT2][4];
#pragma unroll
    for (int n = 0; n < NT2; ++n)
#pragma unroll
        for (int c = 0; c < 4; ++c) oacc[n][c] = 0.f;
    float dg0 = 0.f, dg1 = 0.f;

    uint32_t koff = (uint32_t)(((lane & 7) + ((lane >> 4) << 3)) * KSTR +
                               ((lane >> 3) & 1) * 8) * 2;
    uint32_t voff = (uint32_t)(((lane & 7) + (((lane >> 3) & 1) << 3)) * KSTR +
                               ((lane >> 4) & 1) * 8) * 2;
    uint32_t ks_sh = (uint32_t)__cvta_generic_to_shared(Ks);
    uint32_t vs_sh = (uint32_t)__cvta_generic_to_shared(Vs);

    const int j0base = blockIdx.y * (NROWS / KSPLIT);
    const int ITER = (NROWS / KSPLIT) / 64;       // 16

    auto prefetch = [&](int s, int j0) {
        const __nv_bfloat16* kg = g_glb + (size_t)j0 * F;
        const __nv_bfloat16* vg = g_hb + (size_t)j0 * F;
#pragma unroll
        for (int i = tid; i < 64 * CH; i += 256) {
            int r = i / CH, c = i % CH;
            cpa16(&Ks[s * TILEB + r * KSTR + c * 8], kg + r * F + c * 8);
            cpa16(&Vs[s * TILEB + r * KSTR + c * 8], vg + r * F + c * 8);
        }
        if (tid < 16) cpa16(&sqs[s * 64 + tid * 4], g_sq + j0 + tid * 4);
    };

    prefetch(0, j0base);
    cpa_commit();

    int cur = 0, nxt = 1;
    for (int it = 0; it < ITER; ++it) {
        if (it + 1 < ITER) {
            prefetch(nxt, j0base + (it + 1) * 64);
            cpa_commit();
            cpa_wait<1>();
        } else {
            cpa_wait<0>();
        }
        __syncthreads();

        uint32_t kbase = ks_sh + (uint32_t)(cur * TILEB * 2) + koff;
        uint32_t vbase = vs_sh + (uint32_t)(cur * TILEB * 2) + voff;
        const float* sqsp = sqs + cur * 64;

        // Interleaved: for each 16-key pair -> S gemm, sigmoid, PV gemm.
#pragma unroll
        for (int ntp = 0; ntp < 4; ++ntp) {
            float sacc[2][4];
#pragma unroll
            for (int c = 0; c < 4; ++c) { sacc[0][c] = 0.f; sacc[1][c] = 0.f; }
#pragma unroll
            for (int kc = 0; kc < KC; ++kc) {
                uint32_t b0, b1, b2, b3;
                ldsm4(b0, b1, b2, b3,
                      kbase + (uint32_t)((ntp * 16) * KSTR + kc * 16) * 2);
                mma16816(sacc[0], aq[kc], b0, b1);
                mma16816(sacc[1], aq[kc], b2, b3);
            }

            uint32_t ap[4];
#pragma unroll
            for (int half = 0; half < 2; ++half) {
                int nt = 2 * ntp + half;
                float sqj0 = sqsp[nt * 8 + 2 * t];
                float sqj1 = sqsp[nt * 8 + 2 * t + 1];
                float p0 = sigm(sqi0 + sqj0, sacc[half][0], h1, h2);
                float p1 = sigm(sqi0 + sqj1, sacc[half][1], h1, h2);
                float p2 = sigm(sqi1 + sqj0, sacc[half][2], h1, h2);
                float p3 = sigm(sqi1 + sqj1, sacc[half][3], h1, h2);
                dg0 += p0 + p1;
                dg1 += p2 + p3;
                ap[half * 2 + 0] = pack_bf16(p0, p1);
                ap[half * 2 + 1] = pack_bf16(p2, p3);
            }

#pragma unroll
            for (int ntp2 = 0; ntp2 < NT2 / 2; ++ntp2) {
                uint32_t b0, b1, b2, b3;
                ldsm4t(b0, b1, b2, b3,
                       vbase + (uint32_t)((ntp * 16) * KSTR + ntp2 * 16) * 2);
                mma16816(oacc[2 * ntp2],     ap, b0, b1);
                mma16816(oacc[2 * ntp2 + 1], ap, b2, b3);
            }
        }

        cur = nxt;
        nxt = (nxt == 2) ? 0 : nxt + 1;
    }

    float* Op = g_Opart + (size_t)blockIdx.y * NROWS * F;
#pragma unroll
    for (int nt2 = 0; nt2 < NT2; ++nt2) {
        Op[(size_t)qrow0 * F + nt2 * 8 + 2 * t]     = oacc[nt2][0];
        Op[(size_t)qrow0 * F + nt2 * 8 + 2 * t + 1] = oacc[nt2][1];
        Op[(size_t)qrow1 * F + nt2 * 8 + 2 * t]     = oacc[nt2][2];
        Op[(size_t)qrow1 * F + nt2 * 8 + 2 * t + 1] = oacc[nt2][3];
    }
    dg0 += __shfl_xor_sync(0xffffffffu, dg0, 1);
    dg0 += __shfl_xor_sync(0xffffffffu, dg0, 2);
    dg1 += __shfl_xor_sync(0xffffffffu, dg1, 1);
    dg1 += __shfl_xor_sync(0xffffffffu, dg1, 2);
    if (t == 0) {
        g_degpart[blockIdx.y * NROWS + qrow0] = dg0;
        g_degpart[blockIdx.y * NROWS + qrow1] = dg1;
    }
}

// ---------------- layer-0 finalize: xb = bf16(relu(sum O / sum deg)) -------
template <int F>
__global__ void __launch_bounds__(256) finalize_relu_kernel() {
    int i4 = blockIdx.x * 256 + threadIdx.x;      // float4 index over NROWS*F/4
    int row = (i4 * 4) / F;
    float deg = 0.f;
#pragma unroll
    for (int k = 0; k < KSPLIT; ++k) deg += g_degpart[k * NROWS + row];
    float r = 1.f / deg;
    float4 o = make_float4(0.f, 0.f, 0.f, 0.f);
#pragma unroll
    for (int k = 0; k < KSPLIT; ++k) {
        float4 a = ((const float4*)(g_Opart + (size_t)k * NROWS * F))[i4];
        o.x += a.x; o.y += a.y; o.z += a.z; o.w += a.w;
    }
    __nv_bfloat162* d2 = (__nv_bfloat162*)g_xb + i4 * 2;
    d2[0] = __floats2bfloat162_rn(fmaxf(o.x * r, 0.f), fmaxf(o.y * r, 0.f));
    d2[1] = __floats2bfloat162_rn(fmaxf(o.z * r, 0.f), fmaxf(o.w * r, 0.f));
}

// ---------------- final: softmax over 64 cols ------------------------------
__global__ void __launch_bounds__(256) softmax_kernel(float* __restrict__ out) {
    int row = blockIdx.x * 8 + (threadIdx.x >> 5);
    int lane = threadIdx.x & 31;
    float deg = 0.f;
#pragma unroll
    for (int k = 0; k < KSPLIT; ++k) deg += g_degpart[k * NROWS + row];
    float v0 = 0.f, v1 = 0.f;
#pragma unroll
    for (int k = 0; k < KSPLIT; ++k) {
        const float* Op = g_Opart + (size_t)k * NROWS * 64 + (size_t)row * 64;
        v0 += Op[lane];
        v1 += Op[lane + 32];
    }
    v0 /= deg;
    v1 /= deg;
    float m = fmaxf(v0, v1);
#pragma unroll
    for (int o = 16; o; o >>= 1) m = fmaxf(m, __shfl_xor_sync(0xffffffffu, m, o));
    float e0 = __expf(v0 - m), e1 = __expf(v1 - m);
    float s = e0 + e1;
#pragma unroll
    for (int o = 16; o; o >>= 1) s += __shfl_xor_sync(0xffffffffu, s, o);
    out[(size_t)row * 64 + lane] = e0 / s;
    out[(size_t)row * 64 + lane + 32] = e1 / s;
}

// ---------------- launch ---------------------------------------------------
extern "C" void kernel_launch(void* const* d_in, const int* in_sizes, int n_in,
                              void* d_out, int out_size) {
    const float* feat  = (const float*)d_in[0];
    const float* Wgl0  = (const float*)d_in[6];
    const float* bgl0  = (const float*)d_in[7];
    const float* Wgnn0 = (const float*)d_in[8];
    const float* bgnn0 = (const float*)d_in[9];
    const float* Wgl1  = (const float*)d_in[10];
    const float* bgl1  = (const float*)d_in[11];
    const float* Wgnn1 = (const float*)d_in[12];
    const float* bgnn1 = (const float*)d_in[13];
    const float* temp  = (const float*)d_in[14];
    const float* theta = (const float*)d_in[15];
    float* out = (float*)d_out;

    __nv_bfloat16 *p_wgl0, *p_wgnn0, *p_wgl1, *p_wgnn1;
    cudaGetSymbolAddress((void**)&p_wgl0, g_wgl0);
    cudaGetSymbolAddress((void**)&p_wgnn0, g_wgnn0);
    cudaGetSymbolAddress((void**)&p_wgl1, g_wgl1);
    cudaGetSymbolAddress((void**)&p_wgnn1, g_wgnn1);

    const int psm0 = (2 * 128 * 72 + 2 * 64 * 136) * 2;    // 71680 (prep0)
    const int psm1 = (2 * 128 * 72 + 2 * 64 * 72) * 2;     // 55296 (prep1)
    const int asm0 = 6 * 64 * (128 + 8) * 2 + 3 * 64 * 4;  // 105216 (attn F=128, 3-stage)
    const int asm1 = 6 * 64 * (64 + 8) * 2 + 3 * 64 * 4;   // 56064  (attn F=64, 3-stage)
    cudaFuncSetAttribute(prep_mma_kernel<256, 128>,
                         cudaFuncAttributeMaxDynamicSharedMemorySize, psm0);
    cudaFuncSetAttribute(prep_mma_kernel<128, 64>,
                         cudaFuncAttributeMaxDynamicSharedMemorySize, psm1);
    cudaFuncSetAttribute(attn_kernel<128, 2>,
                         cudaFuncAttributeMaxDynamicSharedMemorySize, asm0);
    cudaFuncSetAttribute(attn_kernel<64, 2>,
                         cudaFuncAttributeMaxDynamicSharedMemorySize, asm1);

    dim3 gp(NROWS / 128, 2);
    dim3 ga(NROWS / 128, KSPLIT);

    // Convert feat + all weights to bf16 in ONE launch (544768 float4 total)
    cvt_all_kernel<<<(544768 + 255) / 256, 256>>>(feat, Wgl0, Wgnn0, Wgl1, Wgnn1);

    // Layer 0 (F = 128, DIN = 256)
    prep_mma_kernel<256, 128><<<gp, 256, psm0>>>(p_wgl0, p_wgnn0, bgl0, bgnn0);
    attn_kernel<128, 2><<<ga, 256, asm0>>>(temp, theta);
    finalize_relu_kernel<128><<<NROWS * 128 / 1024, 256>>>();

    // Layer 1 (F = 64, DIN = 128)
    prep_mma_kernel<128, 64><<<gp, 256, psm1>>>(p_wgl1, p_wgnn1, bgl1, bgnn1);
    attn_kernel<64, 2><<<ga, 256, asm1>>>(temp, theta);
    softmax_kernel<<<NROWS / 8, 256>>>(out);
}

// round 13
// speedup vs baseline: 1.0769x; 1.0769x over previous
#include <cuda_runtime.h>
#include <cuda_bf16.h>
#include <cstdint>

// CDGM: two rounds of fused "sigmoid attention" + small GEMMs.
//   gl = relu(x@Wgl+b); sq_i = |gl_i|^2
//   adj_ij = sigmoid(c2 - c1*sqrt(max(sq_i+sq_j-2 gl_i.gl_j,0)+eps))  (c2 if diff==0)
//   x' = (adj @ (x@Wgnn+b)) / rowsum(adj);  relu (layer0);  softmax (end)
// adj never materialized. bf16 mma.sync throughout. The distance bias
// sq_i+sq_j is folded INTO the S-GEMM via 16 extension features:
//   A-row = [-2q, sq_hi_i, sq_lo_i, 1, 1, 0...]   (A ext built in registers)
//   B-row = [ k,  1, 1, sq_hi_j, sq_lo_j, 0...]   (stored in g_glb ext cols)
// so S = sq_i + sq_j - 2 q.k directly; sigmoid path = max,sqrt,fma,tanh,fma.

#define NROWS 8192
#define KSPLIT 4
#define GLSTRMAX 160

// ---------------- scratch (device globals: no allocation allowed) ----------
__device__ __nv_bfloat16 g_xb[NROWS * 256];           // bf16 input
__device__ __nv_bfloat16 g_wgl0[256 * 128];
__device__ __nv_bfloat16 g_wgnn0[256 * 128];
__device__ __nv_bfloat16 g_wgl1[128 * 64];
__device__ __nv_bfloat16 g_wgnn1[128 * 64];
__device__ __nv_bfloat16 g_glb[NROWS * GLSTRMAX];     // gl + ext, stride F+16
__device__ __nv_bfloat16 g_hb [NROWS * 128];          // h, row-major [N,F]
__device__ float g_sq[NROWS];                         // |gl_i|^2 (rounded bf16)
__device__ float g_Opart[KSPLIT * NROWS * 128];       // per-ksplit partial O
__device__ float g_degpart[KSPLIT * NROWS];           // per-ksplit partial deg

// ---------------- helpers --------------------------------------------------
__device__ __forceinline__ void mma16816(float* d, const uint32_t* a,
                                         uint32_t b0, uint32_t b1) {
    asm("mma.sync.aligned.m16n8k16.row.col.f32.bf16.bf16.f32 "
        "{%0,%1,%2,%3}, {%4,%5,%6,%7}, {%8,%9}, {%0,%1,%2,%3};"
        : "+f"(d[0]), "+f"(d[1]), "+f"(d[2]), "+f"(d[3])
        : "r"(a[0]), "r"(a[1]), "r"(a[2]), "r"(a[3]), "r"(b0), "r"(b1));
}

__device__ __forceinline__ void ldsm4(uint32_t& r0, uint32_t& r1, uint32_t& r2,
                                      uint32_t& r3, uint32_t a) {
    asm volatile("ldmatrix.sync.aligned.m8n8.x4.shared.b16 {%0,%1,%2,%3}, [%4];"
                 : "=r"(r0), "=r"(r1), "=r"(r2), "=r"(r3) : "r"(a));
}
__device__ __forceinline__ void ldsm4t(uint32_t& r0, uint32_t& r1, uint32_t& r2,
                                       uint32_t& r3, uint32_t a) {
    asm volatile("ldmatrix.sync.aligned.m8n8.x4.trans.shared.b16 {%0,%1,%2,%3}, [%4];"
                 : "=r"(r0), "=r"(r1), "=r"(r2), "=r"(r3) : "r"(a));
}

__device__ __forceinline__ void cpa16(void* dst, const void* src) {
    uint32_t d = (uint32_t)__cvta_generic_to_shared(dst);
    asm volatile("cp.async.cg.shared.global [%0], [%1], 16;" :: "r"(d), "l"(src));
}
__device__ __forceinline__ void cpa_commit() {
    asm volatile("cp.async.commit_group;");
}
template <int N>
__device__ __forceinline__ void cpa_wait() {
    asm volatile("cp.async.wait_group %0;" :: "n"(N));
}

__device__ __forceinline__ uint32_t pack_bf16(float lo, float hi) {
    uint32_t r;
    asm("cvt.rn.bf16x2.f32 %0, %1, %2;" : "=r"(r) : "f"(hi), "f"(lo));
    return r;
}

// sigmoid of z = c2 - c1*sqrt(d), d = max(s,0); via tanh: h1=c1/2, h2=c2/2.
// (eps + explicit d==0 mask dropped: sqrt(+0)=+0 reproduces the mask limit.)
__device__ __forceinline__ float sigm(float s, float h1, float h2) {
    float d = fmaxf(s, 0.f);
    float u;
    asm("sqrt.approx.f32 %0, %1;" : "=f"(u) : "f"(d));
    float zz = fmaf(-h1, u, h2);
    float t;
    asm("tanh.approx.f32 %0, %1;" : "=f"(t) : "f"(zz));
    return fmaf(0.5f, t, 0.5f);
}

// ---------------- fused fp32 -> bf16 convert (feat + all weights) ----------
__global__ void __launch_bounds__(256) cvt_all_kernel(
    const float* __restrict__ feat,
    const float* __restrict__ wgl0, const float* __restrict__ wgnn0,
    const float* __restrict__ wgl1, const float* __restrict__ wgnn1) {
    int i = blockIdx.x * 256 + threadIdx.x;
    const float* src;
    __nv_bfloat16* dst;
    int off;
    if (i < 524288)      { src = feat;  dst = g_xb;    off = 0; }
    else if (i < 532480) { src = wgl0;  dst = g_wgl0;  off = 524288; }
    else if (i < 540672) { src = wgnn0; dst = g_wgnn0; off = 532480; }
    else if (i < 542720) { src = wgl1;  dst = g_wgl1;  off = 540672; }
    else if (i < 544768) { src = wgnn1; dst = g_wgnn1; off = 542720; }
    else return;
    int j = i - off;
    float4 v = ((const float4*)src)[j];
    __nv_bfloat162* d2 = (__nv_bfloat162*)dst + j * 2;
    d2[0] = __floats2bfloat162_rn(v.x, v.y);
    d2[1] = __floats2bfloat162_rn(v.z, v.w);
}

// ---------------- tensor-core prep -----------------------------------------
// blockIdx.y: 0 => gl (relu + sq + ext cols into g_glb, stride F+16),
//             1 => h (into g_hb, stride F).
template <int K, int F>
__global__ void __launch_bounds__(256) prep_mma_kernel(
    const __nv_bfloat16* __restrict__ wgl, const __nv_bfloat16* __restrict__ wgnn,
    const float* __restrict__ bgl, const float* __restrict__ bgnn) {
    constexpr int KB   = 64;
    constexpr int XSTR = KB + 8;
    constexpr int WSTR = F + 8;
    constexpr int XTB  = 128 * XSTR;
    constexpr int WTB  = KB * WSTR;
    constexpr int NT   = F / 8;
    constexpr int NK   = K / KB;
    constexpr int FE   = F + 16;

    extern __shared__ __align__(16) __nv_bfloat16 psm[];
    __nv_bfloat16* xs = psm;                 // [2][128][XSTR]
    __nv_bfloat16* ws = psm + 2 * XTB;       // [2][KB][WSTR]

    const bool isGl = (blockIdx.y == 0);
    const __nv_bfloat16* W = isGl ? wgl : wgnn;
    const float* bias = isGl ? bgl : bgnn;

    int tid = threadIdx.x, lane = tid & 31, w = tid >> 5;
    int g = lane >> 2, t = lane & 3;
    int rowbase = blockIdx.x * 128;
    const __nv_bfloat16* xb = g_xb;

    uint32_t aoff = (uint32_t)(((lane & 7) + (((lane >> 3) & 1) << 3)) * XSTR +
                               ((lane >> 4) & 1) * 8) * 2;
    uint32_t boff = (uint32_t)(((lane & 7) + (((lane >> 3) & 1) << 3)) * WSTR +
                               ((lane >> 4) & 1) * 8) * 2;
    uint32_t xs_sh = (uint32_t)__cvta_generic_to_shared(xs);
    uint32_t ws_sh = (uint32_t)__cvta_generic_to_shared(ws);

    float acc[NT][4];
#pragma unroll
    for (int n = 0; n < NT; ++n)
#pragma unroll
        for (int c = 0; c < 4; ++c) acc[n][c] = 0.f;

    auto prefetch = [&](int s, int kt) {
#pragma unroll
        for (int i = tid; i < 128 * (KB / 8); i += 256) {
            int r = i / (KB / 8), c = i % (KB / 8);
            cpa16(&xs[s * XTB + r * XSTR + c * 8],
                  xb + (size_t)(rowbase + r) * K + kt + c * 8);
        }
#pragma unroll
        for (int i = tid; i < KB * (F / 8); i += 256) {
            int r = i / (F / 8), c = i % (F / 8);
            cpa16(&ws[s * WTB + r * WSTR + c * 8], W + (size_t)(kt + r) * F + c * 8);
        }
    };

    prefetch(0, 0);
    cpa_commit();

    for (int it = 0; it < NK; ++it) {
        int cur = it & 1;
        if (it + 1 < NK) {
            prefetch(cur ^ 1, (it + 1) * KB);
            cpa_commit();
            cpa_wait<1>();
        } else {
            cpa_wait<0>();
        }
        __syncthreads();

        uint32_t xbase = xs_sh + (uint32_t)(cur * XTB * 2) +
                         (uint32_t)(w * 16 * XSTR * 2) + aoff;
        uint32_t wbase = ws_sh + (uint32_t)(cur * WTB * 2) + boff;

#pragma unroll
        for (int kc = 0; kc < 4; ++kc) {
            uint32_t a[4];
            ldsm4(a[0], a[1], a[2], a[3], xbase + (uint32_t)(kc * 16) * 2);
#pragma unroll
            for (int ntp = 0; ntp < NT / 2; ++ntp) {
                uint32_t b0, b1, b2, b3;
                ldsm4t(b0, b1, b2, b3,
                       wbase + (uint32_t)((kc * 16) * WSTR + ntp * 16) * 2);
                mma16816(acc[2 * ntp],     a, b0, b1);
                mma16816(acc[2 * ntp + 1], a, b2, b3);
            }
        }
        __syncthreads();
    }

    // Epilogue: bias (+relu for gl), bf16 store, fused sq + ext (gl only).
    int r0 = rowbase + w * 16 + g;
    int r1 = r0 + 8;
    float s0 = 0.f, s1 = 0.f;
#pragma unroll
    for (int nt = 0; nt < NT; ++nt) {
        int col = nt * 8 + 2 * t;
        float b0 = bias[col], b1 = bias[col + 1];
        float v00 = acc[nt][0] + b0, v01 = acc[nt][1] + b1;
        float v10 = acc[nt][2] + b0, v11 = acc[nt][3] + b1;
        if (isGl) {
            v00 = fmaxf(v00, 0.f); v01 = fmaxf(v01, 0.f);
            v10 = fmaxf(v10, 0.f); v11 = fmaxf(v11, 0.f);
        }
        uint32_t u0 = pack_bf16(v00, v01);
        uint32_t u1 = pack_bf16(v10, v11);
        if (isGl) {
            *(uint32_t*)(g_glb + (size_t)r0 * FE + col) = u0;
            *(uint32_t*)(g_glb + (size_t)r1 * FE + col) = u1;
            float2 q0 = __bfloat1622float2(*(__nv_bfloat162*)&u0);
            float2 q1 = __bfloat1622float2(*(__nv_bfloat162*)&u1);
            s0 = fmaf(q0.x, q0.x, fmaf(q0.y, q0.y, s0));
            s1 = fmaf(q1.x, q1.x, fmaf(q1.y, q1.y, s1));
        } else {
            *(uint32_t*)(g_hb + (size_t)r0 * F + col) = u0;
            *(uint32_t*)(g_hb + (size_t)r1 * F + col) = u1;
        }
    }
    if (isGl) {
        s0 += __shfl_xor_sync(0xffffffffu, s0, 1);
        s0 += __shfl_xor_sync(0xffffffffu, s0, 2);
        s1 += __shfl_xor_sync(0xffffffffu, s1, 1);
        s1 += __shfl_xor_sync(0xffffffffu, s1, 2);
        if (t == 0) {
            g_sq[r0] = s0;
            g_sq[r1] = s1;
            // ext cols F..F+15: [1, 1, sq_hi, sq_lo, 0 x 12]
            float h0f = __bfloat162float(__float2bfloat16(s0));
            float h1f = __bfloat162float(__float2bfloat16(s1));
            uint32_t* e0 = (uint32_t*)(g_glb + (size_t)r0 * FE + F);
            uint32_t* e1 = (uint32_t*)(g_glb + (size_t)r1 * FE + F);
            e0[0] = pack_bf16(1.f, 1.f);
            e0[1] = pack_bf16(s0, s0 - h0f);
            e1[0] = pack_bf16(1.f, 1.f);
            e1[1] = pack_bf16(s1, s1 - h1f);
#pragma unroll
            for (int j = 2; j < 8; ++j) { e0[j] = 0u; e1[j] = 0u; }
        }
    }
}

// ---------------- fused sigmoid-attention ----------------------------------
// BR=128, BC=64, grid (N/128, KSPLIT=4). 3-stage cp.async ring, one barrier
// per iter. S-GEMM contracts over F+16 (distance bias folded into MMA).
template <int F, int MINB>
__global__ void __launch_bounds__(256, MINB) attn_kernel(const float* __restrict__ temp,
                                                         const float* __restrict__ theta) {
    constexpr int FE    = F + 16;
    constexpr int KSTRK = FE + 8;
    constexpr int KSTRV = F + 8;
    constexpr int TILEK = 64 * KSTRK;
    constexpr int TILEV = 64 * KSTRV;
    constexpr int KC  = F / 16;           // +1 ext chunk handled below
    constexpr int NT2 = F / 8;
    constexpr int CHK = FE / 8;
    constexpr int CHV = F / 8;

    extern __shared__ __align__(16) __nv_bfloat16 dsm[];
    __nv_bfloat16* Ks = dsm;                      // [3][64][KSTRK]
    __nv_bfloat16* Vs = dsm + 3 * TILEK;          // [3][64][KSTRV]

    int tid = threadIdx.x, lane = tid & 31, w = tid >> 5;
    int g = lane >> 2, t = lane & 3;
    int qrow0 = blockIdx.x * 128 + w * 16 + g;
    int qrow1 = qrow0 + 8;
    float h1 = 0.5f * (1.f + __ldg(temp)), h2 = 0.5f * (5.f + __ldg(theta));

    // Q fragments: -2*q (exact bf16 scale) + register-built ext chunk.
    uint32_t aq[KC + 1][4];
    {
        __nv_bfloat162 m2 = __floats2bfloat162_rn(-2.f, -2.f);
#pragma unroll
        for (int kc = 0; kc < KC; ++kc) {
            const __nv_bfloat16* q0 = g_glb + (size_t)qrow0 * FE + kc * 16 + 2 * t;
            const __nv_bfloat16* q1 = g_glb + (size_t)qrow1 * FE + kc * 16 + 2 * t;
            __nv_bfloat162 v0 = __hmul2(*(const __nv_bfloat162*)q0, m2);
            __nv_bfloat162 v1 = __hmul2(*(const __nv_bfloat162*)q1, m2);
            __nv_bfloat162 v2 = __hmul2(*(const __nv_bfloat162*)(q0 + 8), m2);
            __nv_bfloat162 v3 = __hmul2(*(const __nv_bfloat162*)(q1 + 8), m2);
            aq[kc][0] = *(uint32_t*)&v0;
            aq[kc][1] = *(uint32_t*)&v1;
            aq[kc][2] = *(uint32_t*)&v2;
            aq[kc][3] = *(uint32_t*)&v3;
        }
        float sqi0 = g_sq[qrow0], sqi1 = g_sq[qrow1];
        float hi0 = __bfloat162float(__float2bfloat16(sqi0));
        float hi1 = __bfloat162float(__float2bfloat16(sqi1));
        uint32_t e0 = (t == 0) ? pack_bf16(sqi0, sqi0 - hi0)
                   : (t == 1) ? pack_bf16(1.f, 1.f) : 0u;
        uint32_t e1 = (t == 0) ? pack_bf16(sqi1, sqi1 - hi1)
                   : (t == 1) ? pack_bf16(1.f, 1.f) : 0u;
        aq[KC][0] = e0;
        aq[KC][1] = e1;
        aq[KC][2] = 0u;
        aq[KC][3] = 0u;
    }

    float oacc[NT2][4];
#pragma unroll
    for (int n = 0; n < NT2; ++n)
#pragma unroll
        for (int c = 0; c < 4; ++c) oacc[n][c] = 0.f;
    float dg0 = 0.f, dg1 = 0.f;

    uint32_t koff = (uint32_t)(((lane & 7) + ((lane >> 4) << 3)) * KSTRK +
                               ((lane >> 3) & 1) * 8) * 2;
    uint32_t voff = (uint32_t)(((lane & 7) + (((lane >> 3) & 1) << 3)) * KSTRV +
                               ((lane >> 4) & 1) * 8) * 2;
    uint32_t ks_sh = (uint32_t)__cvta_generic_to_shared(Ks);
    uint32_t vs_sh = (uint32_t)__cvta_generic_to_shared(Vs);

    const int j0base = blockIdx.y * (NROWS / KSPLIT);
    const int ITER = (NROWS / KSPLIT) / 64;       // 32

    auto prefetch = [&](int s, int j0) {
        const __nv_bfloat16* kg = g_glb + (size_t)j0 * FE;
        const __nv_bfloat16* vg = g_hb + (size_t)j0 * F;
#pragma unroll
        for (int i = tid; i < 64 * CHK; i += 256) {
            int r = i / CHK, c = i % CHK;
            cpa16(&Ks[s * TILEK + r * KSTRK + c * 8], kg + (size_t)r * FE + c * 8);
        }
#pragma unroll
        for (int i = tid; i < 64 * CHV; i += 256) {
            int r = i / CHV, c = i % CHV;
            cpa16(&Vs[s * TILEV + r * KSTRV + c * 8], vg + (size_t)r * F + c * 8);
        }
    };

    prefetch(0, j0base);
    cpa_commit();

    int cur = 0, nxt = 1;
    for (int it = 0; it < ITER; ++it) {
        if (it + 1 < ITER) {
            prefetch(nxt, j0base + (it + 1) * 64);
            cpa_commit();
            cpa_wait<1>();
        } else {
            cpa_wait<0>();
        }
        __syncthreads();

        uint32_t kbase = ks_sh + (uint32_t)(cur * TILEK * 2) + koff;
        uint32_t vbase = vs_sh + (uint32_t)(cur * TILEV * 2) + voff;

        // Interleaved: per 16-key pair -> S gemm (incl ext), sigmoid, PV gemm.
#pragma unroll
        for (int ntp = 0; ntp < 4; ++ntp) {
            float sacc[2][4];
#pragma unroll
            for (int c = 0; c < 4; ++c) { sacc[0][c] = 0.f; sacc[1][c] = 0.f; }
#pragma unroll
            for (int kc = 0; kc <= KC; ++kc) {
                uint32_t b0, b1, b2, b3;
                ldsm4(b0, b1, b2, b3,
                      kbase + (uint32_t)((ntp * 16) * KSTRK + kc * 16) * 2);
                mma16816(sacc[0], aq[kc], b0, b1);
                mma16816(sacc[1], aq[kc], b2, b3);
            }

            uint32_t ap[4];
#pragma unroll
            for (int half = 0; half < 2; ++half) {
                float p0 = sigm(sacc[half][0], h1, h2);
                float p1 = sigm(sacc[half][1], h1, h2);
                float p2 = sigm(sacc[half][2], h1, h2);
                float p3 = sigm(sacc[half][3], h1, h2);
                dg0 += p0 + p1;
                dg1 += p2 + p3;
                ap[half * 2 + 0] = pack_bf16(p0, p1);
                ap[half * 2 + 1] = pack_bf16(p2, p3);
            }

#pragma unroll
            for (int ntp2 = 0; ntp2 < NT2 / 2; ++ntp2) {
                uint32_t b0, b1, b2, b3;
                ldsm4t(b0, b1, b2, b3,
                       vbase + (uint32_t)((ntp * 16) * KSTRV + ntp2 * 16) * 2);
                mma16816(oacc[2 * ntp2],     ap, b0, b1);
                mma16816(oacc[2 * ntp2 + 1], ap, b2, b3);
            }
        }

        cur = nxt;
        nxt = (nxt == 2) ? 0 : nxt + 1;
    }

    float* Op = g_Opart + (size_t)blockIdx.y * NROWS * F;
#pragma unroll
    for (int nt2 = 0; nt2 < NT2; ++nt2) {
        Op[(size_t)qrow0 * F + nt2 * 8 + 2 * t]     = oacc[nt2][0];
        Op[(size_t)qrow0 * F + nt2 * 8 + 2 * t + 1] = oacc[nt2][1];
        Op[(size_t)qrow1 * F + nt2 * 8 + 2 * t]     = oacc[nt2][2];
        Op[(size_t)qrow1 * F + nt2 * 8 + 2 * t + 1] = oacc[nt2][3];
    }
    dg0 += __shfl_xor_sync(0xffffffffu, dg0, 1);
    dg0 += __shfl_xor_sync(0xffffffffu, dg0, 2);
    dg1 += __shfl_xor_sync(0xffffffffu, dg1, 1);
    dg1 += __shfl_xor_sync(0xffffffffu, dg1, 2);
    if (t == 0) {
        g_degpart[blockIdx.y * NROWS + qrow0] = dg0;
        g_degpart[blockIdx.y * NROWS + qrow1] = dg1;
    }
}

// ---------------- layer-0 finalize: xb = bf16(relu(sum O / sum deg)) -------
template <int F>
__global__ void __launch_bounds__(256) finalize_relu_kernel() {
    int i4 = blockIdx.x * 256 + threadIdx.x;
    int row = (i4 * 4) / F;
    float deg = 0.f;
#pragma unroll
    for (int k = 0; k < KSPLIT; ++k) deg += g_degpart[k * NROWS + row];
    float r = 1.f / deg;
    float4 o = make_float4(0.f, 0.f, 0.f, 0.f);
#pragma unroll
    for (int k = 0; k < KSPLIT; ++k) {
        float4 a = ((const float4*)(g_Opart + (size_t)k * NROWS * F))[i4];
        o.x += a.x; o.y += a.y; o.z += a.z; o.w += a.w;
    }
    __nv_bfloat162* d2 = (__nv_bfloat162*)g_xb + i4 * 2;
    d2[0] = __floats2bfloat162_rn(fmaxf(o.x * r, 0.f), fmaxf(o.y * r, 0.f));
    d2[1] = __floats2bfloat162_rn(fmaxf(o.z * r, 0.f), fmaxf(o.w * r, 0.f));
}

// ---------------- final: softmax over 64 cols ------------------------------
__global__ void __launch_bounds__(256) softmax_kernel(float* __restrict__ out) {
    int row = blockIdx.x * 8 + (threadIdx.x >> 5);
    int lane = threadIdx.x & 31;
    float deg = 0.f;
#pragma unroll
    for (int k = 0; k < KSPLIT; ++k) deg += g_degpart[k * NROWS + row];
    float v0 = 0.f, v1 = 0.f;
#pragma unroll
    for (int k = 0; k < KSPLIT; ++k) {
        const float* Op = g_Opart + (size_t)k * NROWS * 64 + (size_t)row * 64;
        v0 += Op[lane];
        v1 += Op[lane + 32];
    }
    v0 /= deg;
    v1 /= deg;
    float m = fmaxf(v0, v1);
#pragma unroll
    for (int o = 16; o; o >>= 1) m = fmaxf(m, __shfl_xor_sync(0xffffffffu, m, o));
    float e0 = __expf(v0 - m), e1 = __expf(v1 - m);
    float s = e0 + e1;
#pragma unroll
    for (int o = 16; o; o >>= 1) s += __shfl_xor_sync(0xffffffffu, s, o);
    out[(size_t)row * 64 + lane] = e0 / s;
    out[(size_t)row * 64 + lane + 32] = e1 / s;
}

// ---------------- launch ---------------------------------------------------
extern "C" void kernel_launch(void* const* d_in, const int* in_sizes, int n_in,
                              void* d_out, int out_size) {
    const float* feat  = (const float*)d_in[0];
    const float* Wgl0  = (const float*)d_in[6];
    const float* bgl0  = (const float*)d_in[7];
    const float* Wgnn0 = (const float*)d_in[8];
    const float* bgnn0 = (const float*)d_in[9];
    const float* Wgl1  = (const float*)d_in[10];
    const float* bgl1  = (const float*)d_in[11];
    const float* Wgnn1 = (const float*)d_in[12];
    const float* bgnn1 = (const float*)d_in[13];
    const float* temp  = (const float*)d_in[14];
    const float* theta = (const float*)d_in[15];
    float* out = (float*)d_out;

    __nv_bfloat16 *p_wgl0, *p_wgnn0, *p_wgl1, *p_wgnn1;
    cudaGetSymbolAddress((void**)&p_wgl0, g_wgl0);
    cudaGetSymbolAddress((void**)&p_wgnn0, g_wgnn0);
    cudaGetSymbolAddress((void**)&p_wgl1, g_wgl1);
    cudaGetSymbolAddress((void**)&p_wgnn1, g_wgnn1);

    const int psm0 = (2 * 128 * 72 + 2 * 64 * 136) * 2;       // 71680 (prep0)
    const int psm1 = (2 * 128 * 72 + 2 * 64 * 72) * 2;        // 55296 (prep1)
    const int asm0 = (3 * 64 * 152 + 3 * 64 * 136) * 2;       // 110592 (attn F=128)
    const int asm1 = (3 * 64 * 88 + 3 * 64 * 72) * 2;         // 61440  (attn F=64)
    cudaFuncSetAttribute(prep_mma_kernel<256, 128>,
                         cudaFuncAttributeMaxDynamicSharedMemorySize, psm0);
    cudaFuncSetAttribute(prep_mma_kernel<128, 64>,
                         cudaFuncAttributeMaxDynamicSharedMemorySize, psm1);
    cudaFuncSetAttribute(attn_kernel<128, 2>,
                         cudaFuncAttributeMaxDynamicSharedMemorySize, asm0);
    cudaFuncSetAttribute(attn_kernel<64, 2>,
                         cudaFuncAttributeMaxDynamicSharedMemorySize, asm1);

    dim3 gp(NROWS / 128, 2);
    dim3 ga(NROWS / 128, KSPLIT);

    cvt_all_kernel<<<(544768 + 255) / 256, 256>>>(feat, Wgl0, Wgnn0, Wgl1, Wgnn1);

    // Layer 0 (F = 128, DIN = 256)
    prep_mma_kernel<256, 128><<<gp, 256, psm0>>>(p_wgl0, p_wgnn0, bgl0, bgnn0);
    attn_kernel<128, 2><<<ga, 256, asm0>>>(temp, theta);
    finalize_relu_kernel<128><<<NROWS * 128 / 1024, 256>>>();

    // Layer 1 (F = 64, DIN = 128)
    prep_mma_kernel<128, 64><<<gp, 256, psm1>>>(p_wgl1, p_wgnn1, bgl1, bgnn1);
    attn_kernel<64, 2><<<ga, 256, asm1>>>(temp, theta);
    softmax_kernel<<<NROWS / 8, 256>>>(out);
}